// round 1
// baseline (speedup 1.0000x reference)
#include <cuda_runtime.h>
#include <cuda_bf16.h>
#include <math.h>

// Problem constants (fixed shapes per reference)
#define S_LEN 4096
#define E_DIM 1024
#define E3    3072
#define NHEAD 16
#define HDIM  64
#define QBLK  128

// Scratch (device globals; no allocation allowed)
__device__ float g_qkv[S_LEN * E3];     // [S, 3E]
__device__ float g_ctx[S_LEN * E_DIM];  // [S, E] attention output

// ---------------------------------------------------------------------------
// GEMM: C[M,N] = A[M,K] @ B[N,K]^T + bias[N]     (both row-major, K-contig)
// 128x128 tile, BK=16, 256 threads, 8x8 per-thread register tile.
// ---------------------------------------------------------------------------
#define GBM 128
#define GBN 128
#define GBK 16

__global__ __launch_bounds__(256) void gemm_nt_bias(
    const float* __restrict__ A, const float* __restrict__ B,
    const float* __restrict__ bias, float* __restrict__ C,
    int M, int N, int K)
{
    __shared__ float As[GBK][GBM];   // transposed: [k][m]
    __shared__ float Bs[GBK][GBN];   // transposed: [k][n]

    const int tid = threadIdx.x;
    const int tx = tid & 15;        // 0..15 -> n groups of 8
    const int ty = tid >> 4;        // 0..15 -> m groups of 8
    const int bm = blockIdx.y * GBM;
    const int bn = blockIdx.x * GBN;

    const int lr = tid >> 2;         // 0..63
    const int lc = (tid & 3) * 4;    // 0,4,8,12

    float acc[8][8];
#pragma unroll
    for (int i = 0; i < 8; i++)
#pragma unroll
        for (int j = 0; j < 8; j++) acc[i][j] = 0.f;

    for (int k0 = 0; k0 < K; k0 += GBK) {
#pragma unroll
        for (int h = 0; h < 2; ++h) {
            int r = lr + h * 64;
            float4 va = *(const float4*)(A + (size_t)(bm + r) * K + k0 + lc);
            As[lc + 0][r] = va.x; As[lc + 1][r] = va.y;
            As[lc + 2][r] = va.z; As[lc + 3][r] = va.w;
            float4 vb = *(const float4*)(B + (size_t)(bn + r) * K + k0 + lc);
            Bs[lc + 0][r] = vb.x; Bs[lc + 1][r] = vb.y;
            Bs[lc + 2][r] = vb.z; Bs[lc + 3][r] = vb.w;
        }
        __syncthreads();

#pragma unroll
        for (int kk = 0; kk < GBK; ++kk) {
            float a[8], b[8];
            float4 t;
            t = *(const float4*)&As[kk][ty * 8];     a[0]=t.x; a[1]=t.y; a[2]=t.z; a[3]=t.w;
            t = *(const float4*)&As[kk][ty * 8 + 4]; a[4]=t.x; a[5]=t.y; a[6]=t.z; a[7]=t.w;
            t = *(const float4*)&Bs[kk][tx * 8];     b[0]=t.x; b[1]=t.y; b[2]=t.z; b[3]=t.w;
            t = *(const float4*)&Bs[kk][tx * 8 + 4]; b[4]=t.x; b[5]=t.y; b[6]=t.z; b[7]=t.w;
#pragma unroll
            for (int i = 0; i < 8; i++)
#pragma unroll
                for (int j = 0; j < 8; j++)
                    acc[i][j] += a[i] * b[j];
        }
        __syncthreads();
    }

#pragma unroll
    for (int i = 0; i < 8; i++) {
        int r = bm + ty * 8 + i;
#pragma unroll
        for (int j = 0; j < 8; j += 4) {
            int c = bn + tx * 8 + j;
            float4 v = make_float4(acc[i][j+0] + bias[c+0],
                                   acc[i][j+1] + bias[c+1],
                                   acc[i][j+2] + bias[c+2],
                                   acc[i][j+3] + bias[c+3]);
            *(float4*)(C + (size_t)r * N + c) = v;
        }
    }
}

// ---------------------------------------------------------------------------
// Block-causal flash attention.
// Grid: (32 q-blocks [heaviest first], 16 heads). 256 threads (16x16).
// Each thread: 8 q-rows (ty*8..), S-tile cols tx*8.., O cols tx*4..
// Block mask aligns exactly with 128-wide KV tiles -> no intra-tile mask.
// ---------------------------------------------------------------------------
#define LDQ 132
#define LDV 68
#define LDP 132
#define ATTN_SMEM ((64*LDQ + 64*LDQ + 128*LDV + 128*LDP) * 4)

__global__ __launch_bounds__(256) void attn_kernel(
    const float* __restrict__ qkv, float* __restrict__ ctx)
{
    extern __shared__ float sm[];
    float* Qs = sm;                 // [64][LDQ]  (d-major)
    float* Ks = Qs + 64 * LDQ;      // [64][LDQ]  (d-major)
    float* Vs = Ks + 64 * LDQ;      // [128][LDV] (row-major k,d)
    float* Ps = Vs + 128 * LDV;     // [128][LDP] (q,k)

    const int tid = threadIdx.x;
    const int tx = tid & 15;
    const int ty = tid >> 4;
    const int h = blockIdx.y;
    const int qb = (int)gridDim.x - 1 - (int)blockIdx.x;  // heavy blocks first
    const float scale = 0.125f;  // 1/sqrt(64)

    // Load Q (transposed, pre-scaled)
    const float* Qg = qkv + (size_t)(qb * QBLK) * E3 + h * HDIM;
    for (int idx = tid; idx < QBLK * HDIM; idx += 256) {
        int r = idx >> 6, d = idx & 63;
        Qs[d * LDQ + r] = Qg[(size_t)r * E3 + d] * scale;
    }

    float m_run[8], l_run[8], o[8][4];
#pragma unroll
    for (int i = 0; i < 8; i++) {
        m_run[i] = -1e30f; l_run[i] = 0.f;
#pragma unroll
        for (int c = 0; c < 4; c++) o[i][c] = 0.f;
    }

    for (int j = 0; j <= qb; ++j) {
        __syncthreads();  // prev PV done before overwriting K/V
        const float* Kg = qkv + (size_t)(j * QBLK) * E3 + E_DIM + h * HDIM;
        const float* Vg = qkv + (size_t)(j * QBLK) * E3 + 2 * E_DIM + h * HDIM;
        for (int idx = tid; idx < QBLK * HDIM; idx += 256) {
            int r = idx >> 6, d = idx & 63;
            Ks[d * LDQ + r] = Kg[(size_t)r * E3 + d];
            Vs[r * LDV + d] = Vg[(size_t)r * E3 + d];
        }
        __syncthreads();

        // S = (Q*scale) @ K^T   -> s[8][8]
        float s[8][8];
#pragma unroll
        for (int i = 0; i < 8; i++)
#pragma unroll
            for (int jj = 0; jj < 8; jj++) s[i][jj] = 0.f;

#pragma unroll 8
        for (int kk = 0; kk < 64; ++kk) {
            float a[8], b[8];
            float4 t;
            t = *(const float4*)&Qs[kk * LDQ + ty * 8];     a[0]=t.x; a[1]=t.y; a[2]=t.z; a[3]=t.w;
            t = *(const float4*)&Qs[kk * LDQ + ty * 8 + 4]; a[4]=t.x; a[5]=t.y; a[6]=t.z; a[7]=t.w;
            t = *(const float4*)&Ks[kk * LDQ + tx * 8];     b[0]=t.x; b[1]=t.y; b[2]=t.z; b[3]=t.w;
            t = *(const float4*)&Ks[kk * LDQ + tx * 8 + 4]; b[4]=t.x; b[5]=t.y; b[6]=t.z; b[7]=t.w;
#pragma unroll
            for (int i = 0; i < 8; i++)
#pragma unroll
                for (int jj = 0; jj < 8; jj++)
                    s[i][jj] += a[i] * b[jj];
        }

        // Online softmax (row spread across 16 lanes of same ty)
#pragma unroll
        for (int i = 0; i < 8; i++) {
            float mi = s[i][0];
#pragma unroll
            for (int jj = 1; jj < 8; jj++) mi = fmaxf(mi, s[i][jj]);
#pragma unroll
            for (int off = 1; off < 16; off <<= 1)
                mi = fmaxf(mi, __shfl_xor_sync(0xffffffffu, mi, off));
            float m_new = fmaxf(m_run[i], mi);
            float alpha = __expf(m_run[i] - m_new);
            float rs = 0.f;
#pragma unroll
            for (int jj = 0; jj < 8; jj++) {
                s[i][jj] = __expf(s[i][jj] - m_new);
                rs += s[i][jj];
            }
#pragma unroll
            for (int off = 1; off < 16; off <<= 1)
                rs += __shfl_xor_sync(0xffffffffu, rs, off);
            l_run[i] = l_run[i] * alpha + rs;
            m_run[i] = m_new;
#pragma unroll
            for (int c = 0; c < 4; c++) o[i][c] *= alpha;
            float4 p0 = make_float4(s[i][0], s[i][1], s[i][2], s[i][3]);
            float4 p1 = make_float4(s[i][4], s[i][5], s[i][6], s[i][7]);
            *(float4*)&Ps[(ty * 8 + i) * LDP + tx * 8]     = p0;
            *(float4*)&Ps[(ty * 8 + i) * LDP + tx * 8 + 4] = p1;
        }
        __syncthreads();

        // O += P @ V
#pragma unroll 4
        for (int kk = 0; kk < 128; ++kk) {
            float4 v = *(const float4*)&Vs[kk * LDV + tx * 4];
#pragma unroll
            for (int i = 0; i < 8; i++) {
                float p = Ps[(ty * 8 + i) * LDP + kk];
                o[i][0] += p * v.x; o[i][1] += p * v.y;
                o[i][2] += p * v.z; o[i][3] += p * v.w;
            }
        }
    }

    // Epilogue: normalize and write ctx[S, E]
#pragma unroll
    for (int i = 0; i < 8; i++) {
        float inv = 1.f / l_run[i];
        int r = qb * QBLK + ty * 8 + i;
        float4 v = make_float4(o[i][0] * inv, o[i][1] * inv,
                               o[i][2] * inv, o[i][3] * inv);
        *(float4*)(ctx + (size_t)r * E_DIM + h * HDIM + tx * 4) = v;
    }
}

// ---------------------------------------------------------------------------
extern "C" void kernel_launch(void* const* d_in, const int* in_sizes, int n_in,
                              void* d_out, int out_size)
{
    const float* x      = (const float*)d_in[0];   // [1,4096,1024]
    const float* w_in   = (const float*)d_in[1];   // [3072,1024]
    const float* b_in   = (const float*)d_in[2];   // [3072]
    const float* w_out  = (const float*)d_in[3];   // [1024,1024]
    const float* b_out  = (const float*)d_in[4];   // [1024]
    float* out = (float*)d_out;                    // [1,4096,1024]

    float* qkv = nullptr;
    float* ctx = nullptr;
    cudaGetSymbolAddress((void**)&qkv, g_qkv);
    cudaGetSymbolAddress((void**)&ctx, g_ctx);

    cudaFuncSetAttribute(attn_kernel,
                         cudaFuncAttributeMaxDynamicSharedMemorySize, ATTN_SMEM);

    // 1) QKV projection: [4096,1024] @ [3072,1024]^T + bias -> [4096,3072]
    {
        dim3 grid(E3 / GBN, S_LEN / GBM);
        gemm_nt_bias<<<grid, 256>>>(x, w_in, b_in, qkv, S_LEN, E3, E_DIM);
    }

    // 2) Block-causal attention -> ctx [4096,1024]
    {
        dim3 grid(S_LEN / QBLK, NHEAD);
        attn_kernel<<<grid, 256, ATTN_SMEM>>>(qkv, ctx);
    }

    // 3) Out projection: [4096,1024] @ [1024,1024]^T + bias -> out
    {
        dim3 grid(E_DIM / GBN, S_LEN / GBM);
        gemm_nt_bias<<<grid, 256>>>(ctx, w_out, b_out, out, S_LEN, E_DIM, E_DIM);
    }
}

// round 3
// speedup vs baseline: 1.3085x; 1.3085x over previous
#include <cuda_runtime.h>
#include <cuda_bf16.h>
#include <cstdint>
#include <math.h>

// Problem constants
#define S_LEN 4096
#define E_DIM 1024
#define E3    3072
#define NHEAD 16
#define HDIM  64
#define QBLK  128

// ---------------------------------------------------------------------------
// Scratch (device globals; allocation is forbidden)
// ---------------------------------------------------------------------------
__device__ float          g_qkv[S_LEN * E3];       // fp32 QKV [S, 3E]
__device__ __nv_bfloat16  g_xhi[S_LEN * E_DIM];
__device__ __nv_bfloat16  g_xlo[S_LEN * E_DIM];
__device__ __nv_bfloat16  g_w1hi[E3 * E_DIM];
__device__ __nv_bfloat16  g_w1lo[E3 * E_DIM];
__device__ __nv_bfloat16  g_w2hi[E_DIM * E_DIM];
__device__ __nv_bfloat16  g_w2lo[E_DIM * E_DIM];
__device__ __nv_bfloat16  g_chi[S_LEN * E_DIM];    // attention out hi
__device__ __nv_bfloat16  g_clo[S_LEN * E_DIM];    // attention out lo

// ---------------------------------------------------------------------------
// Helpers
// ---------------------------------------------------------------------------
__device__ __forceinline__ uint32_t smem_u32(const void* p) {
    uint32_t a;
    asm("{ .reg .u64 t; cvta.to.shared.u64 t, %1; cvt.u32.u64 %0, t; }"
        : "=r"(a) : "l"(p));
    return a;
}

__device__ __forceinline__ void ldsm4(uint32_t r[4], uint32_t addr) {
    asm volatile("ldmatrix.sync.aligned.m8n8.x4.shared.b16 {%0,%1,%2,%3}, [%4];"
                 : "=r"(r[0]), "=r"(r[1]), "=r"(r[2]), "=r"(r[3]) : "r"(addr));
}

__device__ __forceinline__ void mma_bf16(float c[4], const uint32_t a[4],
                                         const uint32_t b[2]) {
    asm volatile("mma.sync.aligned.m16n8k16.row.col.f32.bf16.bf16.f32 "
                 "{%0,%1,%2,%3}, {%4,%5,%6,%7}, {%8,%9}, {%0,%1,%2,%3};"
                 : "+f"(c[0]), "+f"(c[1]), "+f"(c[2]), "+f"(c[3])
                 : "r"(a[0]), "r"(a[1]), "r"(a[2]), "r"(a[3]),
                   "r"(b[0]), "r"(b[1]));
}

// f32x2 packed helpers
typedef unsigned long long u64;
__device__ __forceinline__ u64 splat2(float x) {
    u64 r; asm("mov.b64 %0, {%1, %1};" : "=l"(r) : "f"(x)); return r;
}
__device__ __forceinline__ void fma2(u64& d, u64 a, u64 b) {
    asm("fma.rn.f32x2 %0, %1, %2, %3;" : "=l"(d) : "l"(a), "l"(b), "l"(d));
}
__device__ __forceinline__ void mul2(u64& d, u64 a) {
    asm("mul.rn.f32x2 %0, %1, %2;" : "=l"(d) : "l"(d), "l"(a));
}
__device__ __forceinline__ float2 unpk2(u64 v) {
    float2 f; asm("mov.b64 {%0, %1}, %2;" : "=f"(f.x), "=f"(f.y) : "l"(v)); return f;
}

// ---------------------------------------------------------------------------
// fp32 -> bf16 hi/lo split
// ---------------------------------------------------------------------------
__global__ void split_kernel(const float* __restrict__ src,
                             __nv_bfloat16* __restrict__ hi,
                             __nv_bfloat16* __restrict__ lo, int n)
{
    int i = (blockIdx.x * blockDim.x + threadIdx.x) * 4;
    if (i >= n) return;
    float4 v = *(const float4*)(src + i);
    float f[4] = {v.x, v.y, v.z, v.w};
    __nv_bfloat16 h[4], l[4];
#pragma unroll
    for (int k = 0; k < 4; k++) {
        h[k] = __float2bfloat16(f[k]);
        l[k] = __float2bfloat16(f[k] - __bfloat162float(h[k]));
    }
    *(__nv_bfloat162*)(hi + i)     = __nv_bfloat162(h[0], h[1]);
    *(__nv_bfloat162*)(hi + i + 2) = __nv_bfloat162(h[2], h[3]);
    *(__nv_bfloat162*)(lo + i)     = __nv_bfloat162(l[0], l[1]);
    *(__nv_bfloat162*)(lo + i + 2) = __nv_bfloat162(l[2], l[3]);
}

// ---------------------------------------------------------------------------
// mma.sync bf16x3 GEMM: C[M,N] = (Ahi+Alo)[M,K] @ (Bhi+Blo)[N,K]^T + bias[N]
// CTA tile 128x128, 8 warps in 2(m) x 4(n), warp tile 64x32.
// K chunk = 32 bf16, 3-stage cp.async pipeline.
// smem rows padded to 80B (stride 5 x 16B mod 8 -> conflict-free ldmatrix).
// ---------------------------------------------------------------------------
#define KC 32                    // bf16 per K chunk
#define ROWB 80                  // padded row bytes (64 data + 16 pad)
#define MATB (128 * ROWB)        // one matrix tile: 10240 B
#define STAGEB (4 * MATB)        // Ahi Alo Bhi Blo: 40960 B
#define NSTAGE 3
#define GEMM_SMEM (NSTAGE * STAGEB)

__global__ __launch_bounds__(256) void gemm_mma(
    const __nv_bfloat16* __restrict__ Ahi, const __nv_bfloat16* __restrict__ Alo,
    const __nv_bfloat16* __restrict__ Bhi, const __nv_bfloat16* __restrict__ Blo,
    const float* __restrict__ bias, float* __restrict__ C,
    int M, int N, int K)
{
    extern __shared__ char smem[];
    const uint32_t sb = smem_u32(smem);
    const int tid = threadIdx.x;
    const int lane = tid & 31;
    const int wid = tid >> 5;
    const int wm = wid & 1;        // 0..1 (m block of 64)
    const int wn = wid >> 1;       // 0..3 (n block of 32)
    const int bm = blockIdx.y * 128;
    const int bn = blockIdx.x * 128;

    // copy mapping: thread -> (row, half-row of 32B)
    const int cr = tid >> 1;          // 0..127
    const int chalf = tid & 1;        // 0..1

    const __nv_bfloat16* srcs[4] = {
        Ahi + (size_t)(bm + cr) * K,
        Alo + (size_t)(bm + cr) * K,
        Bhi + (size_t)(bn + cr) * K,
        Blo + (size_t)(bn + cr) * K
    };

    auto copy_stage = [&](int c, int buf) {
        uint32_t dst = sb + buf * STAGEB + cr * ROWB + chalf * 32;
        size_t soff = (size_t)c * (KC * 2) + chalf * 32;   // bytes within row
#pragma unroll
        for (int t = 0; t < 4; t++) {
            const char* sp = (const char*)srcs[t] + soff;
            uint32_t dp = dst + t * MATB;
            asm volatile("cp.async.cg.shared.global [%0], [%1], 16;"
                         :: "r"(dp), "l"(sp));
            asm volatile("cp.async.cg.shared.global [%0], [%1], 16;"
                         :: "r"(dp + 16), "l"(sp + 16));
        }
    };

    // ldmatrix per-lane offsets
    const uint32_t aoff = (uint32_t)((wm * 64 + (lane & 15)) * ROWB + (lane >> 4) * 16);
    const uint32_t boff = (uint32_t)((wn * 32 + ((lane >> 4) << 3) + (lane & 7)) * ROWB
                                     + ((lane >> 3) & 1) * 16);

    float acc[4][4][4];
#pragma unroll
    for (int mt = 0; mt < 4; mt++)
#pragma unroll
        for (int nt = 0; nt < 4; nt++)
#pragma unroll
            for (int e = 0; e < 4; e++) acc[mt][nt][e] = 0.f;

    const int NC = K / KC;

    // prologue: stages 0,1
    copy_stage(0, 0);
    asm volatile("cp.async.commit_group;");
    copy_stage(1, 1);
    asm volatile("cp.async.commit_group;");

    for (int c = 0; c < NC; ++c) {
        if (c + 1 < NC) asm volatile("cp.async.wait_group 1;");
        else            asm volatile("cp.async.wait_group 0;");
        __syncthreads();
        if (c + 2 < NC) {
            copy_stage(c + 2, (c + 2) % NSTAGE);
            asm volatile("cp.async.commit_group;");
        }

        const uint32_t sbase = sb + (c % NSTAGE) * STAGEB;
        const uint32_t aHiB = sbase + aoff;            // Ahi; Alo at +MATB
        const uint32_t bHiB = sbase + 2 * MATB + boff; // Bhi; Blo at +MATB

#pragma unroll
        for (int ks = 0; ks < 2; ++ks) {
            uint32_t bh[8], bl[8];
            ldsm4(bh,     bHiB + ks * 32);
            ldsm4(bh + 4, bHiB + 16 * ROWB + ks * 32);
            ldsm4(bl,     bHiB + MATB + ks * 32);
            ldsm4(bl + 4, bHiB + MATB + 16 * ROWB + ks * 32);
#pragma unroll
            for (int mt = 0; mt < 4; ++mt) {
                uint32_t ah[4], al[4];
                ldsm4(ah, aHiB + mt * (16 * ROWB) + ks * 32);
                ldsm4(al, aHiB + MATB + mt * (16 * ROWB) + ks * 32);
#pragma unroll
                for (int nt = 0; nt < 4; ++nt) {
                    mma_bf16(acc[mt][nt], ah, &bh[nt * 2]);   // hi*hi
                    mma_bf16(acc[mt][nt], ah, &bl[nt * 2]);   // hi*lo
                    mma_bf16(acc[mt][nt], al, &bh[nt * 2]);   // lo*hi
                }
            }
        }
    }

    // epilogue
    const int g = lane >> 2;       // row within tile
    const int t2 = (lane & 3) * 2; // col pair within 8
#pragma unroll
    for (int mt = 0; mt < 4; ++mt) {
        int row0 = bm + wm * 64 + mt * 16 + g;
#pragma unroll
        for (int nt = 0; nt < 4; ++nt) {
            int col = bn + wn * 32 + nt * 8 + t2;
            float2 b2 = *(const float2*)&bias[col];
            float2 v0 = make_float2(acc[mt][nt][0] + b2.x, acc[mt][nt][1] + b2.y);
            float2 v1 = make_float2(acc[mt][nt][2] + b2.x, acc[mt][nt][3] + b2.y);
            *(float2*)(C + (size_t)row0 * N + col) = v0;
            *(float2*)(C + (size_t)(row0 + 8) * N + col) = v1;
        }
    }
}

// ---------------------------------------------------------------------------
// Block-causal flash attention (SIMT, f32x2 packed math).
// Grid: (32 q-blocks heavy-first, 16 heads), 256 threads (16x16).
// Writes ctx as bf16 hi/lo split for the out-projection.
// ---------------------------------------------------------------------------
#define LDQ 132
#define LDV 68
#define LDP 132
#define ATTN_SMEM ((64*LDQ + 64*LDQ + 128*LDV + 128*LDP) * 4)

__global__ __launch_bounds__(256) void attn_kernel(
    const float* __restrict__ qkv,
    __nv_bfloat16* __restrict__ chi, __nv_bfloat16* __restrict__ clo)
{
    extern __shared__ float sm[];
    float* Qs = sm;                 // [64][LDQ] d-major
    float* Ks = Qs + 64 * LDQ;      // [64][LDQ] d-major
    float* Vs = Ks + 64 * LDQ;      // [128][LDV] (k, d)
    float* Ps = Vs + 128 * LDV;     // [128][LDP] (q, k)

    const int tid = threadIdx.x;
    const int tx = tid & 15;
    const int ty = tid >> 4;
    const int h = blockIdx.y;
    const int qb = (int)gridDim.x - 1 - (int)blockIdx.x;
    const float scale = 0.125f;

    const float* Qg = qkv + (size_t)(qb * QBLK) * E3 + h * HDIM;
    for (int idx = tid; idx < QBLK * HDIM; idx += 256) {
        int r = idx >> 6, d = idx & 63;
        Qs[d * LDQ + r] = Qg[(size_t)r * E3 + d] * scale;
    }

    float m_run[8], l_run[8];
    u64 o2[8][2];
#pragma unroll
    for (int i = 0; i < 8; i++) {
        m_run[i] = -1e30f; l_run[i] = 0.f;
        o2[i][0] = 0ull; o2[i][1] = 0ull;
    }

    for (int j = 0; j <= qb; ++j) {
        __syncthreads();
        const float* Kg = qkv + (size_t)(j * QBLK) * E3 + E_DIM + h * HDIM;
        const float* Vg = qkv + (size_t)(j * QBLK) * E3 + 2 * E_DIM + h * HDIM;
        for (int idx = tid; idx < QBLK * HDIM; idx += 256) {
            int r = idx >> 6, d = idx & 63;
            Ks[d * LDQ + r] = Kg[(size_t)r * E3 + d];
            Vs[r * LDV + d] = Vg[(size_t)r * E3 + d];
        }
        __syncthreads();

        // S = Q @ K^T  (packed: key-pairs in f32x2 lanes)
        u64 s2[8][4];
#pragma unroll
        for (int i = 0; i < 8; i++)
#pragma unroll
            for (int jj = 0; jj < 4; jj++) s2[i][jj] = 0ull;

#pragma unroll 4
        for (int kk = 0; kk < 64; ++kk) {
            float a[8];
            float4 t;
            t = *(const float4*)&Qs[kk * LDQ + ty * 8];     a[0]=t.x; a[1]=t.y; a[2]=t.z; a[3]=t.w;
            t = *(const float4*)&Qs[kk * LDQ + ty * 8 + 4]; a[4]=t.x; a[5]=t.y; a[6]=t.z; a[7]=t.w;
            ulonglong2 b01 = *(const ulonglong2*)&Ks[kk * LDQ + tx * 8];
            ulonglong2 b23 = *(const ulonglong2*)&Ks[kk * LDQ + tx * 8 + 4];
#pragma unroll
            for (int i = 0; i < 8; i++) {
                u64 as = splat2(a[i]);
                fma2(s2[i][0], as, b01.x);
                fma2(s2[i][1], as, b01.y);
                fma2(s2[i][2], as, b23.x);
                fma2(s2[i][3], as, b23.y);
            }
        }

        // online softmax
#pragma unroll
        for (int i = 0; i < 8; i++) {
            float s[8];
#pragma unroll
            for (int jj = 0; jj < 4; jj++) {
                float2 f = unpk2(s2[i][jj]);
                s[2 * jj] = f.x; s[2 * jj + 1] = f.y;
            }
            float mi = s[0];
#pragma unroll
            for (int jj = 1; jj < 8; jj++) mi = fmaxf(mi, s[jj]);
#pragma unroll
            for (int off = 1; off < 16; off <<= 1)
                mi = fmaxf(mi, __shfl_xor_sync(0xffffffffu, mi, off));
            float m_new = fmaxf(m_run[i], mi);
            float alpha = __expf(m_run[i] - m_new);
            float rs = 0.f;
#pragma unroll
            for (int jj = 0; jj < 8; jj++) {
                s[jj] = __expf(s[jj] - m_new);
                rs += s[jj];
            }
#pragma unroll
            for (int off = 1; off < 16; off <<= 1)
                rs += __shfl_xor_sync(0xffffffffu, rs, off);
            l_run[i] = l_run[i] * alpha + rs;
            m_run[i] = m_new;
            u64 av = splat2(alpha);
            mul2(o2[i][0], av); mul2(o2[i][1], av);
            *(float4*)&Ps[(ty * 8 + i) * LDP + tx * 8]     = make_float4(s[0], s[1], s[2], s[3]);
            *(float4*)&Ps[(ty * 8 + i) * LDP + tx * 8 + 4] = make_float4(s[4], s[5], s[6], s[7]);
        }
        __syncthreads();

        // O += P @ V  (packed d-pairs)
#pragma unroll 2
        for (int kk = 0; kk < 128; kk += 2) {
            ulonglong2 v0 = *(const ulonglong2*)&Vs[kk * LDV + tx * 4];
            ulonglong2 v1 = *(const ulonglong2*)&Vs[(kk + 1) * LDV + tx * 4];
#pragma unroll
            for (int i = 0; i < 8; i++) {
                float2 p = *(const float2*)&Ps[(ty * 8 + i) * LDP + kk];
                u64 p0 = splat2(p.x), p1 = splat2(p.y);
                fma2(o2[i][0], p0, v0.x); fma2(o2[i][1], p0, v0.y);
                fma2(o2[i][0], p1, v1.x); fma2(o2[i][1], p1, v1.y);
            }
        }
    }

    // epilogue: normalize, split to bf16 hi/lo, write ctx
#pragma unroll
    for (int i = 0; i < 8; i++) {
        float inv = 1.f / l_run[i];
        int r = qb * QBLK + ty * 8 + i;
        float2 f0 = unpk2(o2[i][0]), f1 = unpk2(o2[i][1]);
        float v[4] = {f0.x * inv, f0.y * inv, f1.x * inv, f1.y * inv};
        __nv_bfloat16 hh[4], ll[4];
#pragma unroll
        for (int c = 0; c < 4; c++) {
            hh[c] = __float2bfloat16(v[c]);
            ll[c] = __float2bfloat16(v[c] - __bfloat162float(hh[c]));
        }
        size_t off = (size_t)r * E_DIM + h * HDIM + tx * 4;
        *(__nv_bfloat162*)(chi + off)     = __nv_bfloat162(hh[0], hh[1]);
        *(__nv_bfloat162*)(chi + off + 2) = __nv_bfloat162(hh[2], hh[3]);
        *(__nv_bfloat162*)(clo + off)     = __nv_bfloat162(ll[0], ll[1]);
        *(__nv_bfloat162*)(clo + off + 2) = __nv_bfloat162(ll[2], ll[3]);
    }
}

// ---------------------------------------------------------------------------
extern "C" void kernel_launch(void* const* d_in, const int* in_sizes, int n_in,
                              void* d_out, int out_size)
{
    const float* x     = (const float*)d_in[0];
    const float* w_in  = (const float*)d_in[1];
    const float* b_in  = (const float*)d_in[2];
    const float* w_out = (const float*)d_in[3];
    const float* b_out = (const float*)d_in[4];
    float* out = (float*)d_out;

    float* qkv; __nv_bfloat16 *xhi, *xlo, *w1hi, *w1lo, *w2hi, *w2lo, *chi, *clo;
    cudaGetSymbolAddress((void**)&qkv,  g_qkv);
    cudaGetSymbolAddress((void**)&xhi,  g_xhi);
    cudaGetSymbolAddress((void**)&xlo,  g_xlo);
    cudaGetSymbolAddress((void**)&w1hi, g_w1hi);
    cudaGetSymbolAddress((void**)&w1lo, g_w1lo);
    cudaGetSymbolAddress((void**)&w2hi, g_w2hi);
    cudaGetSymbolAddress((void**)&w2lo, g_w2lo);
    cudaGetSymbolAddress((void**)&chi,  g_chi);
    cudaGetSymbolAddress((void**)&clo,  g_clo);

    cudaFuncSetAttribute(gemm_mma, cudaFuncAttributeMaxDynamicSharedMemorySize, GEMM_SMEM);
    cudaFuncSetAttribute(attn_kernel, cudaFuncAttributeMaxDynamicSharedMemorySize, ATTN_SMEM);

    // 0) fp32 -> bf16 hi/lo splits
    {
        int n;
        n = S_LEN * E_DIM; split_kernel<<<(n/4 + 255)/256, 256>>>(x, xhi, xlo, n);
        n = E3 * E_DIM;    split_kernel<<<(n/4 + 255)/256, 256>>>(w_in, w1hi, w1lo, n);
        n = E_DIM * E_DIM; split_kernel<<<(n/4 + 255)/256, 256>>>(w_out, w2hi, w2lo, n);
    }

    // 1) QKV projection (mma bf16x3): [4096,1024] @ [3072,1024]^T + b
    {
        dim3 grid(E3 / 128, S_LEN / 128);
        gemm_mma<<<grid, 256, GEMM_SMEM>>>(xhi, xlo, w1hi, w1lo, b_in, qkv,
                                           S_LEN, E3, E_DIM);
    }

    // 2) block-causal attention -> ctx bf16 hi/lo
    {
        dim3 grid(S_LEN / QBLK, NHEAD);
        attn_kernel<<<grid, 256, ATTN_SMEM>>>(qkv, chi, clo);
    }

    // 3) out projection (mma bf16x3): [4096,1024] @ [1024,1024]^T + b
    {
        dim3 grid(E_DIM / 128, S_LEN / 128);
        gemm_mma<<<grid, 256, GEMM_SMEM>>>(chi, clo, w2hi, w2lo, b_out, out,
                                           S_LEN, E_DIM, E_DIM);
    }
}

// round 5
// speedup vs baseline: 2.6803x; 2.0483x over previous
#include <cuda_runtime.h>
#include <cuda_bf16.h>
#include <cstdint>
#include <math.h>

// Problem constants
#define S_LEN 4096
#define E_DIM 1024
#define E3    3072
#define NHEAD 16
#define HDIM  64
#define QBLK  128

typedef __nv_bfloat16 bf16;

// ---------------------------------------------------------------------------
// Scratch (device globals; allocation is forbidden)
// ---------------------------------------------------------------------------
__device__ bf16 g_qkvhi[S_LEN * E3];
__device__ bf16 g_qkvlo[S_LEN * E3];
__device__ bf16 g_xhi[S_LEN * E_DIM];
__device__ bf16 g_xlo[S_LEN * E_DIM];
__device__ bf16 g_w1hi[E3 * E_DIM];
__device__ bf16 g_w1lo[E3 * E_DIM];
__device__ bf16 g_w2hi[E_DIM * E_DIM];
__device__ bf16 g_w2lo[E_DIM * E_DIM];
__device__ bf16 g_chi[S_LEN * E_DIM];
__device__ bf16 g_clo[S_LEN * E_DIM];

// ---------------------------------------------------------------------------
// Helpers
// ---------------------------------------------------------------------------
__device__ __forceinline__ uint32_t smem_u32(const void* p) {
    uint32_t a;
    asm("{ .reg .u64 t; cvta.to.shared.u64 t, %1; cvt.u32.u64 %0, t; }"
        : "=r"(a) : "l"(p));
    return a;
}
__device__ __forceinline__ void ldsm4(uint32_t r[4], uint32_t addr) {
    asm volatile("ldmatrix.sync.aligned.m8n8.x4.shared.b16 {%0,%1,%2,%3}, [%4];"
                 : "=r"(r[0]), "=r"(r[1]), "=r"(r[2]), "=r"(r[3]) : "r"(addr));
}
__device__ __forceinline__ void ldsm4t(uint32_t r[4], uint32_t addr) {
    asm volatile("ldmatrix.sync.aligned.m8n8.x4.trans.shared.b16 {%0,%1,%2,%3}, [%4];"
                 : "=r"(r[0]), "=r"(r[1]), "=r"(r[2]), "=r"(r[3]) : "r"(addr));
}
__device__ __forceinline__ void mma_bf16(float c[4], const uint32_t a[4],
                                         const uint32_t b[2]) {
    asm volatile("mma.sync.aligned.m16n8k16.row.col.f32.bf16.bf16.f32 "
                 "{%0,%1,%2,%3}, {%4,%5,%6,%7}, {%8,%9}, {%0,%1,%2,%3};"
                 : "+f"(c[0]), "+f"(c[1]), "+f"(c[2]), "+f"(c[3])
                 : "r"(a[0]), "r"(a[1]), "r"(a[2]), "r"(a[3]),
                   "r"(b[0]), "r"(b[1]));
}
__device__ __forceinline__ float ex2f(float x) {
    float r; asm("ex2.approx.f32 %0, %1;" : "=f"(r) : "f"(x)); return r;
}
// pack {lo=a, hi=b} as bf16x2
__device__ __forceinline__ uint32_t pack_bf2(float a, float b) {
    uint32_t d;
    asm("cvt.rn.bf16x2.f32 %0, %1, %2;" : "=r"(d) : "f"(b), "f"(a));
    return d;
}
__device__ __forceinline__ void split_bf(float f, bf16& h, bf16& l) {
    h = __float2bfloat16(f);
    l = __float2bfloat16(f - __bfloat162float(h));
}

// ---------------------------------------------------------------------------
// fp32 -> bf16 hi/lo split
// ---------------------------------------------------------------------------
__global__ void split_kernel(const float* __restrict__ src,
                             bf16* __restrict__ hi, bf16* __restrict__ lo, int n)
{
    int i = (blockIdx.x * blockDim.x + threadIdx.x) * 4;
    if (i >= n) return;
    float4 v = *(const float4*)(src + i);
    float f[4] = {v.x, v.y, v.z, v.w};
    bf16 h[4], l[4];
#pragma unroll
    for (int k = 0; k < 4; k++) split_bf(f[k], h[k], l[k]);
    *(__nv_bfloat162*)(hi + i)     = __nv_bfloat162(h[0], h[1]);
    *(__nv_bfloat162*)(hi + i + 2) = __nv_bfloat162(h[2], h[3]);
    *(__nv_bfloat162*)(lo + i)     = __nv_bfloat162(l[0], l[1]);
    *(__nv_bfloat162*)(lo + i + 2) = __nv_bfloat162(l[2], l[3]);
}

// ---------------------------------------------------------------------------
// mma.sync bf16x3 GEMM: C[M,N] = (Ahi+Alo)[M,K] @ (Bhi+Blo)[N,K]^T + bias[N]
// CTA 128x128, 8 warps 2(m)x4(n), warp 64x32, KC=32, 2-stage cp.async.
// SPLIT: output bf16 hi/lo with per-column-range scale; else fp32.
// ---------------------------------------------------------------------------
#define KC 32
#define ROWB 80
#define MATB (128 * ROWB)
#define STAGEB (4 * MATB)        // 40960
#define GEMM_SMEM (2 * STAGEB)   // 81920

template<bool SPLIT>
__global__ __launch_bounds__(256) void gemm_mma(
    const bf16* __restrict__ Ahi, const bf16* __restrict__ Alo,
    const bf16* __restrict__ Bhi, const bf16* __restrict__ Blo,
    const float* __restrict__ bias,
    float* __restrict__ Cf, bf16* __restrict__ Chi, bf16* __restrict__ Clo,
    int M, int N, int K, int qcols, float qscale)
{
    extern __shared__ char smem[];
    const uint32_t sb = smem_u32(smem);
    const int tid = threadIdx.x;
    const int lane = tid & 31;
    const int wid = tid >> 5;
    const int wm = wid & 1;
    const int wn = wid >> 1;
    const int bm = blockIdx.y * 128;
    const int bn = blockIdx.x * 128;

    const int cr = tid >> 1;
    const int chalf = tid & 1;

    const bf16* srcs[4] = {
        Ahi + (size_t)(bm + cr) * K, Alo + (size_t)(bm + cr) * K,
        Bhi + (size_t)(bn + cr) * K, Blo + (size_t)(bn + cr) * K
    };

    auto copy_stage = [&](int c, int buf) {
        uint32_t dst = sb + buf * STAGEB + cr * ROWB + chalf * 32;
        size_t soff = (size_t)c * (KC * 2) + chalf * 32;
#pragma unroll
        for (int t = 0; t < 4; t++) {
            const char* sp = (const char*)srcs[t] + soff;
            uint32_t dp = dst + t * MATB;
            asm volatile("cp.async.cg.shared.global [%0], [%1], 16;" :: "r"(dp), "l"(sp));
            asm volatile("cp.async.cg.shared.global [%0], [%1], 16;" :: "r"(dp + 16), "l"(sp + 16));
        }
    };

    const uint32_t aoff = (uint32_t)((wm * 64 + (lane & 15)) * ROWB + (lane >> 4) * 16);
    const uint32_t boff = (uint32_t)((wn * 32 + ((lane >> 4) << 3) + (lane & 7)) * ROWB
                                     + ((lane >> 3) & 1) * 16);

    float acc[4][4][4];
#pragma unroll
    for (int mt = 0; mt < 4; mt++)
#pragma unroll
        for (int nt = 0; nt < 4; nt++)
#pragma unroll
            for (int e = 0; e < 4; e++) acc[mt][nt][e] = 0.f;

    const int NC = K / KC;
    copy_stage(0, 0);
    asm volatile("cp.async.commit_group;");
    copy_stage(1, 1);
    asm volatile("cp.async.commit_group;");

    for (int c = 0; c < NC; ++c) {
        if (c + 1 < NC) asm volatile("cp.async.wait_group 1;");
        else            asm volatile("cp.async.wait_group 0;");
        __syncthreads();

        const uint32_t sbase = sb + (c & 1) * STAGEB;
        const uint32_t aHiB = sbase + aoff;
        const uint32_t bHiB = sbase + 2 * MATB + boff;

#pragma unroll
        for (int ks = 0; ks < 2; ++ks) {
            uint32_t bh[8], bl[8];
            ldsm4(bh,     bHiB + ks * 32);
            ldsm4(bh + 4, bHiB + 16 * ROWB + ks * 32);
            ldsm4(bl,     bHiB + MATB + ks * 32);
            ldsm4(bl + 4, bHiB + MATB + 16 * ROWB + ks * 32);
#pragma unroll
            for (int mt = 0; mt < 4; ++mt) {
                uint32_t ah[4], al[4];
                ldsm4(ah, aHiB + mt * (16 * ROWB) + ks * 32);
                ldsm4(al, aHiB + MATB + mt * (16 * ROWB) + ks * 32);
#pragma unroll
                for (int nt = 0; nt < 4; ++nt) {
                    mma_bf16(acc[mt][nt], ah, &bh[nt * 2]);
                    mma_bf16(acc[mt][nt], ah, &bl[nt * 2]);
                    mma_bf16(acc[mt][nt], al, &bh[nt * 2]);
                }
            }
        }
        if (c + 2 < NC) {
            __syncthreads();
            copy_stage(c + 2, c & 1);
            asm volatile("cp.async.commit_group;");
        }
    }

    const int g = lane >> 2;
    const int t2 = (lane & 3) * 2;
#pragma unroll
    for (int mt = 0; mt < 4; ++mt) {
        int row0 = bm + wm * 64 + mt * 16 + g;
#pragma unroll
        for (int nt = 0; nt < 4; ++nt) {
            int col = bn + wn * 32 + nt * 8 + t2;
            float2 b2 = *(const float2*)&bias[col];
            float f00 = acc[mt][nt][0] + b2.x, f01 = acc[mt][nt][1] + b2.y;
            float f10 = acc[mt][nt][2] + b2.x, f11 = acc[mt][nt][3] + b2.y;
            if (SPLIT) {
                if (col < qcols) { f00 *= qscale; f01 *= qscale; f10 *= qscale; f11 *= qscale; }
                bf16 h0, l0, h1, l1;
                split_bf(f00, h0, l0); split_bf(f01, h1, l1);
                *(__nv_bfloat162*)(Chi + (size_t)row0 * N + col) = __nv_bfloat162(h0, h1);
                *(__nv_bfloat162*)(Clo + (size_t)row0 * N + col) = __nv_bfloat162(l0, l1);
                split_bf(f10, h0, l0); split_bf(f11, h1, l1);
                *(__nv_bfloat162*)(Chi + (size_t)(row0 + 8) * N + col) = __nv_bfloat162(h0, h1);
                *(__nv_bfloat162*)(Clo + (size_t)(row0 + 8) * N + col) = __nv_bfloat162(l0, l1);
            } else {
                *(float2*)(Cf + (size_t)row0 * N + col) = make_float2(f00, f01);
                *(float2*)(Cf + (size_t)(row0 + 8) * N + col) = make_float2(f10, f11);
            }
        }
    }
}

// ---------------------------------------------------------------------------
// MMA flash attention (block-causal, BLK=128 aligned with KV tile).
// Grid (32, 16) heavy-first. 8 warps; warp w owns q rows [w*16, w*16+16).
// Q/K/P all bf16 hi/lo split; S,O accum fp32; softmax in log2 domain
// (q pre-scaled by 0.125*log2e in the QKV GEMM epilogue).
// ---------------------------------------------------------------------------
#define AT_ROWB 144
#define AT_MAT  (128 * AT_ROWB)        // 18432
#define KVSTG   (4 * AT_MAT)           // 73728
#define OFF_QH  0
#define OFF_QL  AT_MAT
#define OFF_ST  (2 * AT_MAT)
#define ATTN_SMEM (OFF_ST + 2 * KVSTG) // 184320

__global__ __launch_bounds__(256) void attn_mma(
    const bf16* __restrict__ qkvhi, const bf16* __restrict__ qkvlo,
    bf16* __restrict__ chi, bf16* __restrict__ clo)
{
    extern __shared__ char smc[];
    const uint32_t sb = smem_u32(smc);
    const int tid = threadIdx.x;
    const int lane = tid & 31;
    const int wm = tid >> 5;
    const int h = blockIdx.y;
    const int qb = 31 - (int)blockIdx.x;
    const int qrow0 = qb * QBLK;

    // A-operand lane map (Q, and V row addressing for ldmatrix.trans)
    const int grp = lane >> 3;
    const int rbase = (lane & 7) + ((grp & 1) << 3);
    const uint32_t cbase = (uint32_t)((grp >> 1) << 4);
    // B-operand lane map (K): reg pairing must be {same n, k / k+8}
    const int krow = ((lane >> 4) << 3) + (lane & 7);
    const uint32_t kcol = (uint32_t)(((lane >> 3) & 1) * 16);

    // ---- issue Q + tile0 loads ----
    {
#pragma unroll
        for (int i = 0; i < 4; i++) {
            int id = tid + i * 256;
            int row = id >> 3, col = id & 7;
            uint32_t d = sb + row * AT_ROWB + col * 16;
            size_t gq = (size_t)(qrow0 + row) * E3 + h * HDIM + col * 8;
            asm volatile("cp.async.cg.shared.global [%0], [%1], 16;"
                         :: "r"(d + OFF_QH), "l"((const char*)(qkvhi + gq)));
            asm volatile("cp.async.cg.shared.global [%0], [%1], 16;"
                         :: "r"(d + OFF_QL), "l"((const char*)(qkvlo + gq)));
        }
    }
    auto load_kv = [&](int j, int st) {
        uint32_t stb = sb + OFF_ST + st * KVSTG;
#pragma unroll
        for (int i = 0; i < 4; i++) {
            int id = tid + i * 256;
            int row = id >> 3, col = id & 7;
            uint32_t d = stb + row * AT_ROWB + col * 16;
            size_t gk = (size_t)(j * QBLK + row) * E3 + E_DIM + h * HDIM + col * 8;
            size_t gv = gk + E_DIM;
            asm volatile("cp.async.cg.shared.global [%0], [%1], 16;"
                         :: "r"(d), "l"((const char*)(qkvhi + gk)));
            asm volatile("cp.async.cg.shared.global [%0], [%1], 16;"
                         :: "r"(d + AT_MAT), "l"((const char*)(qkvlo + gk)));
            asm volatile("cp.async.cg.shared.global [%0], [%1], 16;"
                         :: "r"(d + 2 * AT_MAT), "l"((const char*)(qkvhi + gv)));
            asm volatile("cp.async.cg.shared.global [%0], [%1], 16;"
                         :: "r"(d + 3 * AT_MAT), "l"((const char*)(qkvlo + gv)));
        }
    };
    load_kv(0, 0);
    asm volatile("cp.async.commit_group;");
    asm volatile("cp.async.wait_group 0;");
    __syncthreads();

    // ---- Q fragments (persistent) ----
    uint32_t qh[4][4], ql[4][4];
    {
        uint32_t qaddr = sb + (wm * 16 + rbase) * AT_ROWB + cbase;
#pragma unroll
        for (int kt = 0; kt < 4; kt++) {
            ldsm4(qh[kt], qaddr + OFF_QH + kt * 32);
            ldsm4(ql[kt], qaddr + OFF_QL + kt * 32);
        }
    }

    float o[8][4];
#pragma unroll
    for (int nt = 0; nt < 8; nt++)
#pragma unroll
        for (int e = 0; e < 4; e++) o[nt][e] = 0.f;
    float m0 = -1e30f, m1 = -1e30f, l0 = 0.f, l1 = 0.f;

    for (int j = 0; j <= qb; ++j) {
        if (j > 0) {
            asm volatile("cp.async.wait_group 0;");
        }
        __syncthreads();
        if (j < qb) {
            load_kv(j + 1, (j + 1) & 1);
            asm volatile("cp.async.commit_group;");
        }
        const uint32_t stb = sb + OFF_ST + (j & 1) * KVSTG;

        // ---- S = Q @ K^T (bf16x3) ----
        float c[16][4];
#pragma unroll
        for (int nt = 0; nt < 16; nt++)
#pragma unroll
            for (int e = 0; e < 4; e++) c[nt][e] = 0.f;

#pragma unroll
        for (int kt = 0; kt < 4; kt++) {
#pragma unroll
            for (int P = 0; P < 8; P++) {
                uint32_t ka = stb + (P * 16 + krow) * AT_ROWB + kt * 32 + kcol;
                uint32_t kh[4], kl[4];
                ldsm4(kh, ka);
                ldsm4(kl, ka + AT_MAT);
                mma_bf16(c[2 * P],     qh[kt], &kh[0]);
                mma_bf16(c[2 * P + 1], qh[kt], &kh[2]);
                mma_bf16(c[2 * P],     qh[kt], &kl[0]);
                mma_bf16(c[2 * P + 1], qh[kt], &kl[2]);
                mma_bf16(c[2 * P],     ql[kt], &kh[0]);
                mma_bf16(c[2 * P + 1], ql[kt], &kh[2]);
            }
        }

        // ---- online softmax (log2 domain) ----
        float mx0 = c[0][0], mx1 = c[0][2];
#pragma unroll
        for (int nt = 0; nt < 16; nt++) {
            mx0 = fmaxf(mx0, fmaxf(c[nt][0], c[nt][1]));
            mx1 = fmaxf(mx1, fmaxf(c[nt][2], c[nt][3]));
        }
#pragma unroll
        for (int off = 1; off < 4; off <<= 1) {
            mx0 = fmaxf(mx0, __shfl_xor_sync(0xffffffffu, mx0, off));
            mx1 = fmaxf(mx1, __shfl_xor_sync(0xffffffffu, mx1, off));
        }
        float mn0 = fmaxf(m0, mx0), mn1 = fmaxf(m1, mx1);
        float a0 = ex2f(m0 - mn0), a1 = ex2f(m1 - mn1);
        m0 = mn0; m1 = mn1;
        float s0 = 0.f, s1 = 0.f;
#pragma unroll
        for (int nt = 0; nt < 16; nt++) {
            c[nt][0] = ex2f(c[nt][0] - mn0);
            c[nt][1] = ex2f(c[nt][1] - mn0);
            c[nt][2] = ex2f(c[nt][2] - mn1);
            c[nt][3] = ex2f(c[nt][3] - mn1);
            s0 += c[nt][0] + c[nt][1];
            s1 += c[nt][2] + c[nt][3];
        }
#pragma unroll
        for (int off = 1; off < 4; off <<= 1) {
            s0 += __shfl_xor_sync(0xffffffffu, s0, off);
            s1 += __shfl_xor_sync(0xffffffffu, s1, off);
        }
        l0 = l0 * a0 + s0;
        l1 = l1 * a1 + s1;
#pragma unroll
        for (int nt = 0; nt < 8; nt++) {
            o[nt][0] *= a0; o[nt][1] *= a0;
            o[nt][2] *= a1; o[nt][3] *= a1;
        }

        // ---- O += P @ V (P bf16 hi/lo, V bf16 hi/lo) ----
#pragma unroll
        for (int J = 0; J < 8; J++) {
            uint32_t phi[4], plo[4];
#pragma unroll
            for (int q4 = 0; q4 < 2; q4++) {
#pragma unroll
                for (int rh = 0; rh < 2; rh++) {
                    float p0 = c[2 * J + q4][2 * rh];
                    float p1 = c[2 * J + q4][2 * rh + 1];
                    uint32_t ph = pack_bf2(p0, p1);
                    float r0 = p0 - __uint_as_float(ph << 16);
                    float r1 = p1 - __uint_as_float(ph & 0xffff0000u);
                    phi[q4 * 2 + rh] = ph;
                    plo[q4 * 2 + rh] = pack_bf2(r0, r1);
                }
            }
#pragma unroll
            for (int pr = 0; pr < 4; pr++) {
                uint32_t va = stb + 2 * AT_MAT + (J * 16 + rbase) * AT_ROWB
                              + pr * 32 + cbase;
                uint32_t vh[4], vl[4];
                ldsm4t(vh, va);
                ldsm4t(vl, va + AT_MAT);
                mma_bf16(o[2 * pr],     phi, &vh[0]);
                mma_bf16(o[2 * pr + 1], phi, &vh[2]);
                mma_bf16(o[2 * pr],     phi, &vl[0]);
                mma_bf16(o[2 * pr + 1], phi, &vl[2]);
                mma_bf16(o[2 * pr],     plo, &vh[0]);
                mma_bf16(o[2 * pr + 1], plo, &vh[2]);
            }
        }
    }

    // ---- epilogue ----
    float inv0 = 1.f / l0, inv1 = 1.f / l1;
    const int g = lane >> 2;
    const int cp2 = (lane & 3) * 2;
    int row0 = qrow0 + wm * 16 + g;
#pragma unroll
    for (int nt = 0; nt < 8; nt++) {
        int col = h * HDIM + nt * 8 + cp2;
        bf16 h0, L0, h1, L1;
        split_bf(o[nt][0] * inv0, h0, L0); split_bf(o[nt][1] * inv0, h1, L1);
        *(__nv_bfloat162*)(chi + (size_t)row0 * E_DIM + col) = __nv_bfloat162(h0, h1);
        *(__nv_bfloat162*)(clo + (size_t)row0 * E_DIM + col) = __nv_bfloat162(L0, L1);
        split_bf(o[nt][2] * inv1, h0, L0); split_bf(o[nt][3] * inv1, h1, L1);
        *(__nv_bfloat162*)(chi + (size_t)(row0 + 8) * E_DIM + col) = __nv_bfloat162(h0, h1);
        *(__nv_bfloat162*)(clo + (size_t)(row0 + 8) * E_DIM + col) = __nv_bfloat162(L0, L1);
    }
}

// ---------------------------------------------------------------------------
extern "C" void kernel_launch(void* const* d_in, const int* in_sizes, int n_in,
                              void* d_out, int out_size)
{
    const float* x     = (const float*)d_in[0];
    const float* w_in  = (const float*)d_in[1];
    const float* b_in  = (const float*)d_in[2];
    const float* w_out = (const float*)d_in[3];
    const float* b_out = (const float*)d_in[4];
    float* out = (float*)d_out;

    bf16 *qkvhi, *qkvlo, *xhi, *xlo, *w1hi, *w1lo, *w2hi, *w2lo, *chi, *clo;
    cudaGetSymbolAddress((void**)&qkvhi, g_qkvhi);
    cudaGetSymbolAddress((void**)&qkvlo, g_qkvlo);
    cudaGetSymbolAddress((void**)&xhi,  g_xhi);
    cudaGetSymbolAddress((void**)&xlo,  g_xlo);
    cudaGetSymbolAddress((void**)&w1hi, g_w1hi);
    cudaGetSymbolAddress((void**)&w1lo, g_w1lo);
    cudaGetSymbolAddress((void**)&w2hi, g_w2hi);
    cudaGetSymbolAddress((void**)&w2lo, g_w2lo);
    cudaGetSymbolAddress((void**)&chi,  g_chi);
    cudaGetSymbolAddress((void**)&clo,  g_clo);

    cudaFuncSetAttribute(gemm_mma<true>,  cudaFuncAttributeMaxDynamicSharedMemorySize, GEMM_SMEM);
    cudaFuncSetAttribute(gemm_mma<false>, cudaFuncAttributeMaxDynamicSharedMemorySize, GEMM_SMEM);
    cudaFuncSetAttribute(attn_mma, cudaFuncAttributeMaxDynamicSharedMemorySize, ATTN_SMEM);

    // 0) fp32 -> bf16 hi/lo splits
    {
        int n;
        n = S_LEN * E_DIM; split_kernel<<<(n/4 + 255)/256, 256>>>(x, xhi, xlo, n);
        n = E3 * E_DIM;    split_kernel<<<(n/4 + 255)/256, 256>>>(w_in, w1hi, w1lo, n);
        n = E_DIM * E_DIM; split_kernel<<<(n/4 + 255)/256, 256>>>(w_out, w2hi, w2lo, n);
    }

    const float qscale = 0.125f * 1.44269504088896340736f;  // (1/sqrt(64))*log2(e)

    // 1) QKV projection -> bf16 hi/lo qkv, q cols pre-scaled
    {
        dim3 grid(E3 / 128, S_LEN / 128);
        gemm_mma<true><<<grid, 256, GEMM_SMEM>>>(xhi, xlo, w1hi, w1lo, b_in,
                                                 nullptr, qkvhi, qkvlo,
                                                 S_LEN, E3, E_DIM, E_DIM, qscale);
    }

    // 2) block-causal attention -> ctx bf16 hi/lo
    {
        dim3 grid(S_LEN / QBLK, NHEAD);
        attn_mma<<<grid, 256, ATTN_SMEM>>>(qkvhi, qkvlo, chi, clo);
    }

    // 3) out projection -> fp32 out
    {
        dim3 grid(E_DIM / 128, S_LEN / 128);
        gemm_mma<false><<<grid, 256, GEMM_SMEM>>>(chi, clo, w2hi, w2lo, b_out,
                                                  out, nullptr, nullptr,
                                                  S_LEN, E_DIM, E_DIM, 0, 1.0f);
    }
}

// round 6
// speedup vs baseline: 2.9116x; 1.0863x over previous
#include <cuda_runtime.h>
#include <cuda_bf16.h>
#include <cstdint>
#include <math.h>

// Problem constants
#define S_LEN 4096
#define E_DIM 1024
#define E3    3072
#define NHEAD 16
#define HDIM  64
#define QBLK  128

typedef __nv_bfloat16 bf16;

// ---------------------------------------------------------------------------
// Scratch (device globals; allocation is forbidden)
// ---------------------------------------------------------------------------
__device__ bf16 g_qkvhi[S_LEN * E3];
__device__ bf16 g_qkvlo[S_LEN * E3];
__device__ bf16 g_xhi[S_LEN * E_DIM];
__device__ bf16 g_xlo[S_LEN * E_DIM];
__device__ bf16 g_w1hi[E3 * E_DIM];
__device__ bf16 g_w1lo[E3 * E_DIM];
__device__ bf16 g_w2hi[E_DIM * E_DIM];
__device__ bf16 g_w2lo[E_DIM * E_DIM];
__device__ bf16 g_chi[S_LEN * E_DIM];
__device__ bf16 g_clo[S_LEN * E_DIM];

// ---------------------------------------------------------------------------
// Helpers
// ---------------------------------------------------------------------------
__device__ __forceinline__ uint32_t smem_u32(const void* p) {
    uint32_t a;
    asm("{ .reg .u64 t; cvta.to.shared.u64 t, %1; cvt.u32.u64 %0, t; }"
        : "=r"(a) : "l"(p));
    return a;
}
__device__ __forceinline__ void ldsm4(uint32_t r[4], uint32_t addr) {
    asm volatile("ldmatrix.sync.aligned.m8n8.x4.shared.b16 {%0,%1,%2,%3}, [%4];"
                 : "=r"(r[0]), "=r"(r[1]), "=r"(r[2]), "=r"(r[3]) : "r"(addr));
}
__device__ __forceinline__ void ldsm4t(uint32_t r[4], uint32_t addr) {
    asm volatile("ldmatrix.sync.aligned.m8n8.x4.trans.shared.b16 {%0,%1,%2,%3}, [%4];"
                 : "=r"(r[0]), "=r"(r[1]), "=r"(r[2]), "=r"(r[3]) : "r"(addr));
}
__device__ __forceinline__ void mma_bf16(float c[4], const uint32_t a[4],
                                         const uint32_t b[2]) {
    asm volatile("mma.sync.aligned.m16n8k16.row.col.f32.bf16.bf16.f32 "
                 "{%0,%1,%2,%3}, {%4,%5,%6,%7}, {%8,%9}, {%0,%1,%2,%3};"
                 : "+f"(c[0]), "+f"(c[1]), "+f"(c[2]), "+f"(c[3])
                 : "r"(a[0]), "r"(a[1]), "r"(a[2]), "r"(a[3]),
                   "r"(b[0]), "r"(b[1]));
}
__device__ __forceinline__ float ex2f(float x) {
    float r; asm("ex2.approx.f32 %0, %1;" : "=f"(r) : "f"(x)); return r;
}
// pack {lo=a, hi=b} as bf16x2
__device__ __forceinline__ uint32_t pack_bf2(float a, float b) {
    uint32_t d;
    asm("cvt.rn.bf16x2.f32 %0, %1, %2;" : "=r"(d) : "f"(b), "f"(a));
    return d;
}
__device__ __forceinline__ void split_bf(float f, bf16& h, bf16& l) {
    h = __float2bfloat16(f);
    l = __float2bfloat16(f - __bfloat162float(h));
}

// ---------------------------------------------------------------------------
// fp32 -> bf16 hi/lo split
// ---------------------------------------------------------------------------
__global__ void split_kernel(const float* __restrict__ src,
                             bf16* __restrict__ hi, bf16* __restrict__ lo, int n)
{
    int i = (blockIdx.x * blockDim.x + threadIdx.x) * 4;
    if (i >= n) return;
    float4 v = *(const float4*)(src + i);
    float f[4] = {v.x, v.y, v.z, v.w};
    bf16 h[4], l[4];
#pragma unroll
    for (int k = 0; k < 4; k++) split_bf(f[k], h[k], l[k]);
    *(__nv_bfloat162*)(hi + i)     = __nv_bfloat162(h[0], h[1]);
    *(__nv_bfloat162*)(hi + i + 2) = __nv_bfloat162(h[2], h[3]);
    *(__nv_bfloat162*)(lo + i)     = __nv_bfloat162(l[0], l[1]);
    *(__nv_bfloat162*)(lo + i + 2) = __nv_bfloat162(l[2], l[3]);
}

// ---------------------------------------------------------------------------
// mma.sync bf16x3 GEMM: C[M,N] = (Ahi+Alo)[M,K] @ (Bhi+Blo)[N,K]^T + bias[N]
// CTA 128x128, 8 warps 2(m)x4(n), warp 64x32, KC=32, 2-stage cp.async.
// __launch_bounds__(256, 2): cap regs at 128 so 2 CTAs co-reside per SM.
// SPLIT: output bf16 hi/lo with per-column-range scale; else fp32.
// ---------------------------------------------------------------------------
#define KC 32
#define ROWB 80
#define MATB (128 * ROWB)
#define STAGEB (4 * MATB)        // 40960
#define GEMM_SMEM (2 * STAGEB)   // 81920

template<bool SPLIT>
__global__ __launch_bounds__(256, 2) void gemm_mma(
    const bf16* __restrict__ Ahi, const bf16* __restrict__ Alo,
    const bf16* __restrict__ Bhi, const bf16* __restrict__ Blo,
    const float* __restrict__ bias,
    float* __restrict__ Cf, bf16* __restrict__ Chi, bf16* __restrict__ Clo,
    int M, int N, int K, int qcols, float qscale)
{
    extern __shared__ char smem[];
    const uint32_t sb = smem_u32(smem);
    const int tid = threadIdx.x;
    const int lane = tid & 31;
    const int wid = tid >> 5;
    const int wm = wid & 1;
    const int wn = wid >> 1;
    const int bm = blockIdx.y * 128;
    const int bn = blockIdx.x * 128;

    const int cr = tid >> 1;
    const int chalf = tid & 1;

    const bf16* srcs[4] = {
        Ahi + (size_t)(bm + cr) * K, Alo + (size_t)(bm + cr) * K,
        Bhi + (size_t)(bn + cr) * K, Blo + (size_t)(bn + cr) * K
    };

    auto copy_stage = [&](int c, int buf) {
        uint32_t dst = sb + buf * STAGEB + cr * ROWB + chalf * 32;
        size_t soff = (size_t)c * (KC * 2) + chalf * 32;
#pragma unroll
        for (int t = 0; t < 4; t++) {
            const char* sp = (const char*)srcs[t] + soff;
            uint32_t dp = dst + t * MATB;
            asm volatile("cp.async.cg.shared.global [%0], [%1], 16;" :: "r"(dp), "l"(sp));
            asm volatile("cp.async.cg.shared.global [%0], [%1], 16;" :: "r"(dp + 16), "l"(sp + 16));
        }
    };

    const uint32_t aoff = (uint32_t)((wm * 64 + (lane & 15)) * ROWB + (lane >> 4) * 16);
    const uint32_t boff = (uint32_t)((wn * 32 + ((lane >> 4) << 3) + (lane & 7)) * ROWB
                                     + ((lane >> 3) & 1) * 16);

    float acc[4][4][4];
#pragma unroll
    for (int mt = 0; mt < 4; mt++)
#pragma unroll
        for (int nt = 0; nt < 4; nt++)
#pragma unroll
            for (int e = 0; e < 4; e++) acc[mt][nt][e] = 0.f;

    const int NC = K / KC;
    copy_stage(0, 0);
    asm volatile("cp.async.commit_group;");
    copy_stage(1, 1);
    asm volatile("cp.async.commit_group;");

    for (int c = 0; c < NC; ++c) {
        if (c + 1 < NC) asm volatile("cp.async.wait_group 1;");
        else            asm volatile("cp.async.wait_group 0;");
        __syncthreads();

        const uint32_t sbase = sb + (c & 1) * STAGEB;
        const uint32_t aHiB = sbase + aoff;
        const uint32_t bHiB = sbase + 2 * MATB + boff;

#pragma unroll
        for (int ks = 0; ks < 2; ++ks) {
            uint32_t bh[8], bl[8];
            ldsm4(bh,     bHiB + ks * 32);
            ldsm4(bh + 4, bHiB + 16 * ROWB + ks * 32);
            ldsm4(bl,     bHiB + MATB + ks * 32);
            ldsm4(bl + 4, bHiB + MATB + 16 * ROWB + ks * 32);
#pragma unroll
            for (int mt = 0; mt < 4; ++mt) {
                uint32_t ah[4], al[4];
                ldsm4(ah, aHiB + mt * (16 * ROWB) + ks * 32);
                ldsm4(al, aHiB + MATB + mt * (16 * ROWB) + ks * 32);
#pragma unroll
                for (int nt = 0; nt < 4; ++nt) {
                    mma_bf16(acc[mt][nt], ah, &bh[nt * 2]);
                    mma_bf16(acc[mt][nt], ah, &bl[nt * 2]);
                    mma_bf16(acc[mt][nt], al, &bh[nt * 2]);
                }
            }
        }
        if (c + 2 < NC) {
            __syncthreads();
            copy_stage(c + 2, c & 1);
            asm volatile("cp.async.commit_group;");
        }
    }

    const int g = lane >> 2;
    const int t2 = (lane & 3) * 2;
#pragma unroll
    for (int mt = 0; mt < 4; ++mt) {
        int row0 = bm + wm * 64 + mt * 16 + g;
#pragma unroll
        for (int nt = 0; nt < 4; ++nt) {
            int col = bn + wn * 32 + nt * 8 + t2;
            float2 b2 = *(const float2*)&bias[col];
            float f00 = acc[mt][nt][0] + b2.x, f01 = acc[mt][nt][1] + b2.y;
            float f10 = acc[mt][nt][2] + b2.x, f11 = acc[mt][nt][3] + b2.y;
            if (SPLIT) {
                if (col < qcols) { f00 *= qscale; f01 *= qscale; f10 *= qscale; f11 *= qscale; }
                bf16 h0, l0, h1, l1;
                split_bf(f00, h0, l0); split_bf(f01, h1, l1);
                *(__nv_bfloat162*)(Chi + (size_t)row0 * N + col) = __nv_bfloat162(h0, h1);
                *(__nv_bfloat162*)(Clo + (size_t)row0 * N + col) = __nv_bfloat162(l0, l1);
                split_bf(f10, h0, l0); split_bf(f11, h1, l1);
                *(__nv_bfloat162*)(Chi + (size_t)(row0 + 8) * N + col) = __nv_bfloat162(h0, h1);
                *(__nv_bfloat162*)(Clo + (size_t)(row0 + 8) * N + col) = __nv_bfloat162(l0, l1);
            } else {
                *(float2*)(Cf + (size_t)row0 * N + col) = make_float2(f00, f01);
                *(float2*)(Cf + (size_t)(row0 + 8) * N + col) = make_float2(f10, f11);
            }
        }
    }
}

// ---------------------------------------------------------------------------
// MMA flash attention (block-causal, BLK=128 aligned with KV tile).
// Grid (32, 16) heavy-first. 8 warps; warp w owns q rows [w*16, w*16+16).
// Q/K/P all bf16 hi/lo split; S,O accum fp32; softmax in log2 domain
// (q pre-scaled by 0.125*log2e in the QKV GEMM epilogue).
// ---------------------------------------------------------------------------
#define AT_ROWB 144
#define AT_MAT  (128 * AT_ROWB)        // 18432
#define KVSTG   (4 * AT_MAT)           // 73728
#define OFF_QH  0
#define OFF_QL  AT_MAT
#define OFF_ST  (2 * AT_MAT)
#define ATTN_SMEM (OFF_ST + 2 * KVSTG) // 184320

__global__ __launch_bounds__(256, 1) void attn_mma(
    const bf16* __restrict__ qkvhi, const bf16* __restrict__ qkvlo,
    bf16* __restrict__ chi, bf16* __restrict__ clo)
{
    extern __shared__ char smc[];
    const uint32_t sb = smem_u32(smc);
    const int tid = threadIdx.x;
    const int lane = tid & 31;
    const int wm = tid >> 5;
    const int h = blockIdx.y;
    const int qb = 31 - (int)blockIdx.x;
    const int qrow0 = qb * QBLK;

    // A-operand lane map (Q, and V row addressing for ldmatrix.trans)
    const int grp = lane >> 3;
    const int rbase = (lane & 7) + ((grp & 1) << 3);
    const uint32_t cbase = (uint32_t)((grp >> 1) << 4);
    // B-operand lane map (K): reg pairing must be {same n, k / k+8}
    const int krow = ((lane >> 4) << 3) + (lane & 7);
    const uint32_t kcol = (uint32_t)(((lane >> 3) & 1) * 16);

    // ---- issue Q + tile0 loads ----
    {
#pragma unroll
        for (int i = 0; i < 4; i++) {
            int id = tid + i * 256;
            int row = id >> 3, col = id & 7;
            uint32_t d = sb + row * AT_ROWB + col * 16;
            size_t gq = (size_t)(qrow0 + row) * E3 + h * HDIM + col * 8;
            asm volatile("cp.async.cg.shared.global [%0], [%1], 16;"
                         :: "r"(d + OFF_QH), "l"((const char*)(qkvhi + gq)));
            asm volatile("cp.async.cg.shared.global [%0], [%1], 16;"
                         :: "r"(d + OFF_QL), "l"((const char*)(qkvlo + gq)));
        }
    }
    auto load_kv = [&](int j, int st) {
        uint32_t stb = sb + OFF_ST + st * KVSTG;
#pragma unroll
        for (int i = 0; i < 4; i++) {
            int id = tid + i * 256;
            int row = id >> 3, col = id & 7;
            uint32_t d = stb + row * AT_ROWB + col * 16;
            size_t gk = (size_t)(j * QBLK + row) * E3 + E_DIM + h * HDIM + col * 8;
            size_t gv = gk + E_DIM;
            asm volatile("cp.async.cg.shared.global [%0], [%1], 16;"
                         :: "r"(d), "l"((const char*)(qkvhi + gk)));
            asm volatile("cp.async.cg.shared.global [%0], [%1], 16;"
                         :: "r"(d + AT_MAT), "l"((const char*)(qkvlo + gk)));
            asm volatile("cp.async.cg.shared.global [%0], [%1], 16;"
                         :: "r"(d + 2 * AT_MAT), "l"((const char*)(qkvhi + gv)));
            asm volatile("cp.async.cg.shared.global [%0], [%1], 16;"
                         :: "r"(d + 3 * AT_MAT), "l"((const char*)(qkvlo + gv)));
        }
    };
    load_kv(0, 0);
    asm volatile("cp.async.commit_group;");
    asm volatile("cp.async.wait_group 0;");
    __syncthreads();

    // ---- Q fragments (persistent) ----
    uint32_t qh[4][4], ql[4][4];
    {
        uint32_t qaddr = sb + (wm * 16 + rbase) * AT_ROWB + cbase;
#pragma unroll
        for (int kt = 0; kt < 4; kt++) {
            ldsm4(qh[kt], qaddr + OFF_QH + kt * 32);
            ldsm4(ql[kt], qaddr + OFF_QL + kt * 32);
        }
    }

    float o[8][4];
#pragma unroll
    for (int nt = 0; nt < 8; nt++)
#pragma unroll
        for (int e = 0; e < 4; e++) o[nt][e] = 0.f;
    float m0 = -1e30f, m1 = -1e30f, l0 = 0.f, l1 = 0.f;

    for (int j = 0; j <= qb; ++j) {
        if (j > 0) {
            asm volatile("cp.async.wait_group 0;");
        }
        __syncthreads();
        if (j < qb) {
            load_kv(j + 1, (j + 1) & 1);
            asm volatile("cp.async.commit_group;");
        }
        const uint32_t stb = sb + OFF_ST + (j & 1) * KVSTG;

        // ---- S = Q @ K^T (bf16x3) ----
        float c[16][4];
#pragma unroll
        for (int nt = 0; nt < 16; nt++)
#pragma unroll
            for (int e = 0; e < 4; e++) c[nt][e] = 0.f;

#pragma unroll
        for (int kt = 0; kt < 4; kt++) {
#pragma unroll
            for (int P = 0; P < 8; P++) {
                uint32_t ka = stb + (P * 16 + krow) * AT_ROWB + kt * 32 + kcol;
                uint32_t kh[4], kl[4];
                ldsm4(kh, ka);
                ldsm4(kl, ka + AT_MAT);
                mma_bf16(c[2 * P],     qh[kt], &kh[0]);
                mma_bf16(c[2 * P + 1], qh[kt], &kh[2]);
                mma_bf16(c[2 * P],     qh[kt], &kl[0]);
                mma_bf16(c[2 * P + 1], qh[kt], &kl[2]);
                mma_bf16(c[2 * P],     ql[kt], &kh[0]);
                mma_bf16(c[2 * P + 1], ql[kt], &kh[2]);
            }
        }

        // ---- online softmax (log2 domain) ----
        float mx0 = c[0][0], mx1 = c[0][2];
#pragma unroll
        for (int nt = 0; nt < 16; nt++) {
            mx0 = fmaxf(mx0, fmaxf(c[nt][0], c[nt][1]));
            mx1 = fmaxf(mx1, fmaxf(c[nt][2], c[nt][3]));
        }
#pragma unroll
        for (int off = 1; off < 4; off <<= 1) {
            mx0 = fmaxf(mx0, __shfl_xor_sync(0xffffffffu, mx0, off));
            mx1 = fmaxf(mx1, __shfl_xor_sync(0xffffffffu, mx1, off));
        }
        float mn0 = fmaxf(m0, mx0), mn1 = fmaxf(m1, mx1);
        float a0 = ex2f(m0 - mn0), a1 = ex2f(m1 - mn1);
        m0 = mn0; m1 = mn1;
        float s0 = 0.f, s1 = 0.f;
#pragma unroll
        for (int nt = 0; nt < 16; nt++) {
            c[nt][0] = ex2f(c[nt][0] - mn0);
            c[nt][1] = ex2f(c[nt][1] - mn0);
            c[nt][2] = ex2f(c[nt][2] - mn1);
            c[nt][3] = ex2f(c[nt][3] - mn1);
            s0 += c[nt][0] + c[nt][1];
            s1 += c[nt][2] + c[nt][3];
        }
#pragma unroll
        for (int off = 1; off < 4; off <<= 1) {
            s0 += __shfl_xor_sync(0xffffffffu, s0, off);
            s1 += __shfl_xor_sync(0xffffffffu, s1, off);
        }
        l0 = l0 * a0 + s0;
        l1 = l1 * a1 + s1;
#pragma unroll
        for (int nt = 0; nt < 8; nt++) {
            o[nt][0] *= a0; o[nt][1] *= a0;
            o[nt][2] *= a1; o[nt][3] *= a1;
        }

        // ---- O += P @ V (P bf16 hi/lo, V bf16 hi/lo) ----
#pragma unroll
        for (int J = 0; J < 8; J++) {
            uint32_t phi[4], plo[4];
#pragma unroll
            for (int q4 = 0; q4 < 2; q4++) {
#pragma unroll
                for (int rh = 0; rh < 2; rh++) {
                    float p0 = c[2 * J + q4][2 * rh];
                    float p1 = c[2 * J + q4][2 * rh + 1];
                    uint32_t ph = pack_bf2(p0, p1);
                    float r0 = p0 - __uint_as_float(ph << 16);
                    float r1 = p1 - __uint_as_float(ph & 0xffff0000u);
                    phi[q4 * 2 + rh] = ph;
                    plo[q4 * 2 + rh] = pack_bf2(r0, r1);
                }
            }
#pragma unroll
            for (int pr = 0; pr < 4; pr++) {
                uint32_t va = stb + 2 * AT_MAT + (J * 16 + rbase) * AT_ROWB
                              + pr * 32 + cbase;
                uint32_t vh[4], vl[4];
                ldsm4t(vh, va);
                ldsm4t(vl, va + AT_MAT);
                mma_bf16(o[2 * pr],     phi, &vh[0]);
                mma_bf16(o[2 * pr + 1], phi, &vh[2]);
                mma_bf16(o[2 * pr],     phi, &vl[0]);
                mma_bf16(o[2 * pr + 1], phi, &vl[2]);
                mma_bf16(o[2 * pr],     plo, &vh[0]);
                mma_bf16(o[2 * pr + 1], plo, &vh[2]);
            }
        }
    }

    // ---- epilogue ----
    float inv0 = 1.f / l0, inv1 = 1.f / l1;
    const int g = lane >> 2;
    const int cp2 = (lane & 3) * 2;
    int row0 = qrow0 + wm * 16 + g;
#pragma unroll
    for (int nt = 0; nt < 8; nt++) {
        int col = h * HDIM + nt * 8 + cp2;
        bf16 h0, L0, h1, L1;
        split_bf(o[nt][0] * inv0, h0, L0); split_bf(o[nt][1] * inv0, h1, L1);
        *(__nv_bfloat162*)(chi + (size_t)row0 * E_DIM + col) = __nv_bfloat162(h0, h1);
        *(__nv_bfloat162*)(clo + (size_t)row0 * E_DIM + col) = __nv_bfloat162(L0, L1);
        split_bf(o[nt][2] * inv1, h0, L0); split_bf(o[nt][3] * inv1, h1, L1);
        *(__nv_bfloat162*)(chi + (size_t)(row0 + 8) * E_DIM + col) = __nv_bfloat162(h0, h1);
        *(__nv_bfloat162*)(clo + (size_t)(row0 + 8) * E_DIM + col) = __nv_bfloat162(L0, L1);
    }
}

// ---------------------------------------------------------------------------
extern "C" void kernel_launch(void* const* d_in, const int* in_sizes, int n_in,
                              void* d_out, int out_size)
{
    const float* x     = (const float*)d_in[0];
    const float* w_in  = (const float*)d_in[1];
    const float* b_in  = (const float*)d_in[2];
    const float* w_out = (const float*)d_in[3];
    const float* b_out = (const float*)d_in[4];
    float* out = (float*)d_out;

    bf16 *qkvhi, *qkvlo, *xhi, *xlo, *w1hi, *w1lo, *w2hi, *w2lo, *chi, *clo;
    cudaGetSymbolAddress((void**)&qkvhi, g_qkvhi);
    cudaGetSymbolAddress((void**)&qkvlo, g_qkvlo);
    cudaGetSymbolAddress((void**)&xhi,  g_xhi);
    cudaGetSymbolAddress((void**)&xlo,  g_xlo);
    cudaGetSymbolAddress((void**)&w1hi, g_w1hi);
    cudaGetSymbolAddress((void**)&w1lo, g_w1lo);
    cudaGetSymbolAddress((void**)&w2hi, g_w2hi);
    cudaGetSymbolAddress((void**)&w2lo, g_w2lo);
    cudaGetSymbolAddress((void**)&chi,  g_chi);
    cudaGetSymbolAddress((void**)&clo,  g_clo);

    cudaFuncSetAttribute(gemm_mma<true>,  cudaFuncAttributeMaxDynamicSharedMemorySize, GEMM_SMEM);
    cudaFuncSetAttribute(gemm_mma<false>, cudaFuncAttributeMaxDynamicSharedMemorySize, GEMM_SMEM);
    cudaFuncSetAttribute(attn_mma, cudaFuncAttributeMaxDynamicSharedMemorySize, ATTN_SMEM);

    // 0) fp32 -> bf16 hi/lo splits
    {
        int n;
        n = S_LEN * E_DIM; split_kernel<<<(n/4 + 255)/256, 256>>>(x, xhi, xlo, n);
        n = E3 * E_DIM;    split_kernel<<<(n/4 + 255)/256, 256>>>(w_in, w1hi, w1lo, n);
        n = E_DIM * E_DIM; split_kernel<<<(n/4 + 255)/256, 256>>>(w_out, w2hi, w2lo, n);
    }

    const float qscale = 0.125f * 1.44269504088896340736f;  // (1/sqrt(64))*log2(e)

    // 1) QKV projection -> bf16 hi/lo qkv, q cols pre-scaled
    {
        dim3 grid(E3 / 128, S_LEN / 128);
        gemm_mma<true><<<grid, 256, GEMM_SMEM>>>(xhi, xlo, w1hi, w1lo, b_in,
                                                 nullptr, qkvhi, qkvlo,
                                                 S_LEN, E3, E_DIM, E_DIM, qscale);
    }

    // 2) block-causal attention -> ctx bf16 hi/lo
    {
        dim3 grid(S_LEN / QBLK, NHEAD);
        attn_mma<<<grid, 256, ATTN_SMEM>>>(qkvhi, qkvlo, chi, clo);
    }

    // 3) out projection -> fp32 out
    {
        dim3 grid(E_DIM / 128, S_LEN / 128);
        gemm_mma<false><<<grid, 256, GEMM_SMEM>>>(chi, clo, w2hi, w2lo, b_out,
                                                  out, nullptr, nullptr,
                                                  S_LEN, E_DIM, E_DIM, 0, 1.0f);
    }
}